// round 1
// baseline (speedup 1.0000x reference)
#include <cuda_runtime.h>
#include <math.h>

// Problem dims (fixed by the reference)
#define BD 64
#define SD 128
#define ED 1024
#define HD_ 8       // heads
#define DH 128      // head dim
#define KPD 32      // Linformer k
#define MTOT (BD*SD)   // 8192

// Scratch (device globals — allocation-free rule)
__device__ float g_Q [MTOT*ED];
__device__ float g_K [MTOT*ED];
__device__ float g_V [MTOT*ED];
__device__ float g_AO[MTOT*ED];
__device__ float g_Kp[BD*HD_*KPD*SD];
__device__ float g_Vp[BD*HD_*KPD*SD];

// ---------------------------------------------------------------------------
// C[M,N] = A[M,K] * B[N,K]^T + bias[N]   (both operands K-contiguous, "NT")
// 128x128 block tile, BK=16, 256 threads, 8x8 per-thread micro-tile.
// M,N,K assumed multiples of 128/128/16 (true here).
// ---------------------------------------------------------------------------
__global__ void __launch_bounds__(256) gemm_nt_bias(
    const float* __restrict__ A, const float* __restrict__ Bm,
    const float* __restrict__ bias, float* __restrict__ C,
    int M, int N, int K)
{
    __shared__ float As[16][128];
    __shared__ float Bs[16][128];

    const int bm = blockIdx.y * 128;
    const int bn = blockIdx.x * 128;
    const int tid = threadIdx.x;
    const int tx = tid & 15;
    const int ty = tid >> 4;

    float acc[8][8];
#pragma unroll
    for (int i = 0; i < 8; i++)
#pragma unroll
        for (int j = 0; j < 8; j++) acc[i][j] = 0.f;

    const float* Aptr = A  + (size_t)bm * K;
    const float* Bptr = Bm + (size_t)bn * K;

    for (int k0 = 0; k0 < K; k0 += 16) {
        // Each thread loads 2 float4 from A-tile and 2 from B-tile (transposed into smem)
#pragma unroll
        for (int u = 0; u < 2; u++) {
            int f = tid * 2 + u;          // 0..511
            int r = f >> 2;               // tile row 0..127
            int c = (f & 3) << 2;         // k offset 0,4,8,12
            float4 va = *(const float4*)(Aptr + (size_t)r * K + k0 + c);
            As[c + 0][r] = va.x; As[c + 1][r] = va.y;
            As[c + 2][r] = va.z; As[c + 3][r] = va.w;
            float4 vb = *(const float4*)(Bptr + (size_t)r * K + k0 + c);
            Bs[c + 0][r] = vb.x; Bs[c + 1][r] = vb.y;
            Bs[c + 2][r] = vb.z; Bs[c + 3][r] = vb.w;
        }
        __syncthreads();

#pragma unroll
        for (int k = 0; k < 16; k++) {
            float a[8], b[8];
#pragma unroll
            for (int i = 0; i < 8; i++) a[i] = As[k][ty * 8 + i];
#pragma unroll
            for (int j = 0; j < 8; j++) b[j] = Bs[k][tx * 8 + j];
#pragma unroll
            for (int i = 0; i < 8; i++)
#pragma unroll
                for (int j = 0; j < 8; j++)
                    acc[i][j] = fmaf(a[i], b[j], acc[i][j]);
        }
        __syncthreads();
    }

#pragma unroll
    for (int i = 0; i < 8; i++) {
        int row = bm + ty * 8 + i;
#pragma unroll
        for (int j = 0; j < 8; j += 4) {
            int col = bn + tx * 8 + j;
            float4 o;
            o.x = acc[i][j + 0] + bias[col + 0];
            o.y = acc[i][j + 1] + bias[col + 1];
            o.z = acc[i][j + 2] + bias[col + 2];
            o.w = acc[i][j + 3] + bias[col + 3];
            *(float4*)(C + (size_t)row * N + col) = o;
        }
    }
}

// ---------------------------------------------------------------------------
// K_proj[b,h,i,s] = sum_d P[d,i] * K[b,s,h*128+d]   (same for V)
// One block per (b,h): output 32x128 per matrix. 256 threads, 16 outputs each.
// Chunked over d in steps of 32.
// ---------------------------------------------------------------------------
__global__ void __launch_bounds__(256) proj_kernel(
    const float* __restrict__ Kbuf, const float* __restrict__ Vbuf,
    const float* __restrict__ P,
    float* __restrict__ Kp, float* __restrict__ Vp)
{
    const int bh = blockIdx.x;
    const int b = bh >> 3, h = bh & 7;
    __shared__ float Ps[32][32];    // [dd][i]
    __shared__ float Ks[128][33];   // [s][dd] padded
    __shared__ float Vs[128][33];

    const int tid = threadIdx.x;
    float accK[16], accV[16];
#pragma unroll
    for (int r = 0; r < 16; r++) { accK[r] = 0.f; accV[r] = 0.f; }

    const float* kb = Kbuf + ((size_t)b * SD) * ED + h * DH;
    const float* vb = Vbuf + ((size_t)b * SD) * ED + h * DH;

    for (int d0 = 0; d0 < DH; d0 += 32) {
        // P chunk: 32x32
#pragma unroll
        for (int u = 0; u < 4; u++) {
            int e = tid + 256 * u;
            int dd = e >> 5, i = e & 31;
            Ps[dd][i] = P[(size_t)(d0 + dd) * KPD + i];
        }
        // K,V chunks: 128x32 each
#pragma unroll
        for (int u = 0; u < 16; u++) {
            int e = tid + 256 * u;
            int s = e >> 5, dd = e & 31;
            Ks[s][dd] = kb[(size_t)s * ED + d0 + dd];
            Vs[s][dd] = vb[(size_t)s * ED + d0 + dd];
        }
        __syncthreads();

#pragma unroll
        for (int r = 0; r < 16; r++) {
            int e = tid + 256 * r;
            int i = e >> 7, s = e & 127;
            float ak = accK[r], av = accV[r];
#pragma unroll
            for (int dd = 0; dd < 32; dd++) {
                float p = Ps[dd][i];
                ak = fmaf(p, Ks[s][dd], ak);
                av = fmaf(p, Vs[s][dd], av);
            }
            accK[r] = ak; accV[r] = av;
        }
        __syncthreads();
    }

    const size_t base = (size_t)bh * (KPD * SD);
#pragma unroll
    for (int r = 0; r < 16; r++) {
        int e = tid + 256 * r;
        Kp[base + e] = accK[r];
        Vp[base + e] = accV[r];
    }
}

// ---------------------------------------------------------------------------
// Per-(b,h): scores = Q(128x128) @ Kp(32x128)^T / sqrt(128), softmax over 32,
// out(128x128) = attn @ Vp(32x128); written to AO[b,s,h*128+t].
// 128 threads; thread s owns score row s. attn staged in smem (reuses Kp buf)
// so the output pass is coalesced.
// ---------------------------------------------------------------------------
__global__ void __launch_bounds__(128) attn_kernel(
    const float* __restrict__ Qbuf, const float* __restrict__ Kp,
    const float* __restrict__ Vp, float* __restrict__ AO)
{
    const int bh = blockIdx.x;
    const int b = bh >> 3, h = bh & 7;
    __shared__ float KpA[128 * 33]; // first: Kp [32][128] (4096 fl); later: attn [128][33]
    __shared__ float VpS[32 * 128];
    __shared__ float QS[128][17];   // Q chunk [s][dd], dd=16, padded

    const int tid = threadIdx.x;
    const size_t base = (size_t)bh * (KPD * SD);

#pragma unroll
    for (int u = 0; u < 32; u++) {
        int e = tid + 128 * u;
        KpA[e] = Kp[base + e];
        VpS[e] = Vp[base + e];
    }
    __syncthreads();

    float sc[32];
#pragma unroll
    for (int j = 0; j < 32; j++) sc[j] = 0.f;

    const float* qb = Qbuf + ((size_t)b * SD) * ED + h * DH;

    for (int d0 = 0; d0 < DH; d0 += 16) {
#pragma unroll
        for (int u = 0; u < 16; u++) {
            int e = tid + 128 * u;
            int s = e >> 4, dd = e & 15;
            QS[s][dd] = qb[(size_t)s * ED + d0 + dd];
        }
        __syncthreads();

        float q[16];
#pragma unroll
        for (int dd = 0; dd < 16; dd++) q[dd] = QS[tid][dd];
#pragma unroll
        for (int j = 0; j < 32; j++) {
            float p = 0.f;
#pragma unroll
            for (int dd = 0; dd < 16; dd++)
                p = fmaf(q[dd], KpA[j * 128 + d0 + dd], p);
            sc[j] += p;
        }
        __syncthreads();
    }

    // softmax over 32 (registers)
    const float scale = 0.08838834764831845f;  // 1/sqrt(128)
    float m = -1e30f;
#pragma unroll
    for (int j = 0; j < 32; j++) { sc[j] *= scale; m = fmaxf(m, sc[j]); }
    float sum = 0.f;
#pragma unroll
    for (int j = 0; j < 32; j++) { sc[j] = expf(sc[j] - m); sum += sc[j]; }
    float inv = 1.f / sum;

    // stage attn rows in smem (KpA no longer needed; last read was before loop's
    // trailing __syncthreads)
#pragma unroll
    for (int j = 0; j < 32; j++) KpA[tid * 33 + j] = sc[j] * inv;
    __syncthreads();

    // out[r][tid] = sum_j attn[r][j] * Vp[j][tid] — coalesced writes
    float* ao = AO + ((size_t)b * SD) * ED + h * DH + tid;
    for (int r = 0; r < SD; r++) {
        float acc = 0.f;
#pragma unroll
        for (int j = 0; j < 32; j++)
            acc = fmaf(KpA[r * 33 + j], VpS[j * 128 + tid], acc);
        ao[(size_t)r * ED] = acc;
    }
}

// ---------------------------------------------------------------------------
extern "C" void kernel_launch(void* const* d_in, const int* in_sizes, int n_in,
                              void* d_out, int out_size)
{
    const float* x  = (const float*)d_in[0];
    const float* Wq = (const float*)d_in[1];
    const float* bq = (const float*)d_in[2];
    const float* Wk = (const float*)d_in[3];
    const float* bk = (const float*)d_in[4];
    const float* Wv = (const float*)d_in[5];
    const float* bv = (const float*)d_in[6];
    const float* P  = (const float*)d_in[7];
    const float* Wo = (const float*)d_in[8];
    const float* bo = (const float*)d_in[9];
    float* out = (float*)d_out;

    float *Qp, *Kbp, *Vbp, *AOp, *Kpp, *Vpp;
    cudaGetSymbolAddress((void**)&Qp,  g_Q);
    cudaGetSymbolAddress((void**)&Kbp, g_K);
    cudaGetSymbolAddress((void**)&Vbp, g_V);
    cudaGetSymbolAddress((void**)&AOp, g_AO);
    cudaGetSymbolAddress((void**)&Kpp, g_Kp);
    cudaGetSymbolAddress((void**)&Vpp, g_Vp);

    dim3 ggrid(ED / 128, MTOT / 128);  // (8, 64)

    gemm_nt_bias<<<ggrid, 256>>>(x, Wq, bq, Qp,  MTOT, ED, ED);
    gemm_nt_bias<<<ggrid, 256>>>(x, Wk, bk, Kbp, MTOT, ED, ED);
    gemm_nt_bias<<<ggrid, 256>>>(x, Wv, bv, Vbp, MTOT, ED, ED);

    proj_kernel<<<BD * HD_, 256>>>(Kbp, Vbp, P, Kpp, Vpp);
    attn_kernel<<<BD * HD_, 128>>>(Qp, Kpp, Vpp, AOp);

    gemm_nt_bias<<<ggrid, 256>>>(AOp, Wo, bo, out, MTOT, ED, ED);
}

// round 3
// speedup vs baseline: 2.4072x; 2.4072x over previous
#include <cuda_runtime.h>
#include <cuda_bf16.h>
#include <math.h>

// Problem dims (fixed by the reference)
#define BD 64
#define SD 128
#define ED 1024
#define HD_ 8       // heads
#define DH 128      // head dim
#define KPD 32      // Linformer k
#define MTOT (BD*SD)   // 8192

// Scratch (device globals — allocation-free rule)
__device__ float g_Q [MTOT*ED];
__device__ float g_K [MTOT*ED];
__device__ float g_V [MTOT*ED];
__device__ float g_AO[MTOT*ED];
__device__ float g_Kp[BD*HD_*KPD*SD];
__device__ float g_Vp[BD*HD_*KPD*SD];

// Split x into bf16 hi/lo packed pairs
__device__ __forceinline__ void split2(float x, float y, unsigned& hi, unsigned& lo) {
    __nv_bfloat16 hx = __float2bfloat16_rn(x);
    __nv_bfloat16 hy = __float2bfloat16_rn(y);
    __nv_bfloat16 lx = __float2bfloat16_rn(x - __bfloat162float(hx));
    __nv_bfloat16 ly = __float2bfloat16_rn(y - __bfloat162float(hy));
    __nv_bfloat162 h2 = __nv_bfloat162(hx, hy);
    __nv_bfloat162 l2 = __nv_bfloat162(lx, ly);
    hi = *(unsigned*)&h2;
    lo = *(unsigned*)&l2;
}

__device__ __forceinline__ void mma_bf16(
    float& c0, float& c1, float& c2, float& c3,
    unsigned a0, unsigned a1, unsigned a2, unsigned a3,
    unsigned b0, unsigned b1)
{
    asm volatile(
        "mma.sync.aligned.m16n8k16.row.col.f32.bf16.bf16.f32 "
        "{%0,%1,%2,%3}, {%4,%5,%6,%7}, {%8,%9}, {%0,%1,%2,%3};\n"
        : "+f"(c0), "+f"(c1), "+f"(c2), "+f"(c3)
        : "r"(a0), "r"(a1), "r"(a2), "r"(a3), "r"(b0), "r"(b1));
}

// ---------------------------------------------------------------------------
// Tensor-core GEMM with bf16x3 fp32 emulation:
// C[M,N] = A[M,K] * W[N,K]^T + bias[N]
// Block tile 128x128, BK=32, 256 threads = 8 warps (2 M x 4 N), warp 64x32.
// smem: packed bf16x2 k-pair words, layout [kpair][m], stride 136.
// ---------------------------------------------------------------------------
#define SSTR 136

__global__ void __launch_bounds__(256) gemm_tc(
    const float* __restrict__ A,
    const float* __restrict__ W0, const float* __restrict__ b0p, float* __restrict__ C0,
    const float* __restrict__ W1, const float* __restrict__ b1p, float* __restrict__ C1,
    const float* __restrict__ W2, const float* __restrict__ b2p, float* __restrict__ C2)
{
    const float* W    = (blockIdx.z == 0) ? W0  : (blockIdx.z == 1) ? W1  : W2;
    const float* bias = (blockIdx.z == 0) ? b0p : (blockIdx.z == 1) ? b1p : b2p;
    float*       C    = (blockIdx.z == 0) ? C0  : (blockIdx.z == 1) ? C1  : C2;

    // 16 k-pairs (k=32) x 128 rows, hi+lo, A and B
    __shared__ unsigned AsH[16][SSTR];
    __shared__ unsigned AsL[16][SSTR];
    __shared__ unsigned BsH[16][SSTR];
    __shared__ unsigned BsL[16][SSTR];

    const int tid  = threadIdx.x;
    const int lane = tid & 31;
    const int w    = tid >> 5;
    const int wm   = w >> 2;      // 0..1
    const int wn   = w & 3;       // 0..3
    const int r    = lane >> 2;   // 0..7 (groupID)
    const int cq   = lane & 3;    // 0..3 (threadID in group)

    const int bm = blockIdx.y * 128;
    const int bn = blockIdx.x * 128;

    const float* Aptr = A + (size_t)bm * ED;
    const float* Wptr = W + (size_t)bn * ED;

    float acc[4][4][4];
#pragma unroll
    for (int mt = 0; mt < 4; mt++)
#pragma unroll
        for (int nt = 0; nt < 4; nt++)
#pragma unroll
            for (int i = 0; i < 4; i++) acc[mt][nt][i] = 0.f;

    for (int k0 = 0; k0 < ED; k0 += 32) {
        // Stage 128x32 tiles, bf16-split, packed k-pairs, layout [kpair][m]
#pragma unroll
        for (int u = 0; u < 4; u++) {
            int idx = tid + 256 * u;        // 0..1023
            int row = idx >> 3;             // 0..127
            int cg  = idx & 7;              // k offset cg*4 -> pairs cg*2, cg*2+1
            float4 va = *(const float4*)(Aptr + (size_t)row * ED + k0 + cg * 4);
            unsigned h0, l0, h1, l1;
            split2(va.x, va.y, h0, l0);
            split2(va.z, va.w, h1, l1);
            AsH[cg * 2    ][row] = h0; AsL[cg * 2    ][row] = l0;
            AsH[cg * 2 + 1][row] = h1; AsL[cg * 2 + 1][row] = l1;
            float4 vb = *(const float4*)(Wptr + (size_t)row * ED + k0 + cg * 4);
            split2(vb.x, vb.y, h0, l0);
            split2(vb.z, vb.w, h1, l1);
            BsH[cg * 2    ][row] = h0; BsL[cg * 2    ][row] = l0;
            BsH[cg * 2 + 1][row] = h1; BsL[cg * 2 + 1][row] = l1;
        }
        __syncthreads();

#pragma unroll
        for (int kk = 0; kk < 2; kk++) {     // two k16 steps per k0
            const int kb = kk * 8;           // pair-row base
            unsigned afH[4][4], afL[4][4], bfH[4][2], bfL[4][2];
#pragma unroll
            for (int mt = 0; mt < 4; mt++) {
                int m = wm * 64 + mt * 16 + r;
                afH[mt][0] = AsH[kb + cq    ][m    ];
                afH[mt][1] = AsH[kb + cq    ][m + 8];
                afH[mt][2] = AsH[kb + cq + 4][m    ];
                afH[mt][3] = AsH[kb + cq + 4][m + 8];
                afL[mt][0] = AsL[kb + cq    ][m    ];
                afL[mt][1] = AsL[kb + cq    ][m + 8];
                afL[mt][2] = AsL[kb + cq + 4][m    ];
                afL[mt][3] = AsL[kb + cq + 4][m + 8];
            }
#pragma unroll
            for (int nt = 0; nt < 4; nt++) {
                int n = wn * 32 + nt * 8 + r;
                bfH[nt][0] = BsH[kb + cq    ][n];
                bfH[nt][1] = BsH[kb + cq + 4][n];
                bfL[nt][0] = BsL[kb + cq    ][n];
                bfL[nt][1] = BsL[kb + cq + 4][n];
            }
#pragma unroll
            for (int mt = 0; mt < 4; mt++)
#pragma unroll
                for (int nt = 0; nt < 4; nt++) {
                    // hi*hi + hi*lo + lo*hi  (drop lo*lo)
                    mma_bf16(acc[mt][nt][0], acc[mt][nt][1],
                             acc[mt][nt][2], acc[mt][nt][3],
                             afH[mt][0], afH[mt][1], afH[mt][2], afH[mt][3],
                             bfH[nt][0], bfH[nt][1]);
                    mma_bf16(acc[mt][nt][0], acc[mt][nt][1],
                             acc[mt][nt][2], acc[mt][nt][3],
                             afH[mt][0], afH[mt][1], afH[mt][2], afH[mt][3],
                             bfL[nt][0], bfL[nt][1]);
                    mma_bf16(acc[mt][nt][0], acc[mt][nt][1],
                             acc[mt][nt][2], acc[mt][nt][3],
                             afL[mt][0], afL[mt][1], afL[mt][2], afL[mt][3],
                             bfH[nt][0], bfH[nt][1]);
                }
        }
        __syncthreads();
    }

    // Epilogue: bias add + store
#pragma unroll
    for (int nt = 0; nt < 4; nt++) {
        int col = bn + wn * 32 + nt * 8 + cq * 2;
        float bb0 = __ldg(bias + col);
        float bb1 = __ldg(bias + col + 1);
#pragma unroll
        for (int mt = 0; mt < 4; mt++) {
            int row = bm + wm * 64 + mt * 16 + r;
            float2 v0 = make_float2(acc[mt][nt][0] + bb0, acc[mt][nt][1] + bb1);
            float2 v1 = make_float2(acc[mt][nt][2] + bb0, acc[mt][nt][3] + bb1);
            *(float2*)(C + (size_t)row * ED + col)       = v0;
            *(float2*)(C + (size_t)(row + 8) * ED + col) = v1;
        }
    }
}

// ---------------------------------------------------------------------------
// K_proj[b,h,i,s] = sum_d P[d,i] * K[b,s,h*128+d]   (same for V)
// ---------------------------------------------------------------------------
__global__ void __launch_bounds__(256) proj_kernel(
    const float* __restrict__ Kbuf, const float* __restrict__ Vbuf,
    const float* __restrict__ P,
    float* __restrict__ Kp, float* __restrict__ Vp)
{
    const int bh = blockIdx.x;
    const int b = bh >> 3, h = bh & 7;
    __shared__ float Ps[32][32];
    __shared__ float Ks[128][33];
    __shared__ float Vs[128][33];

    const int tid = threadIdx.x;
    float accK[16], accV[16];
#pragma unroll
    for (int r = 0; r < 16; r++) { accK[r] = 0.f; accV[r] = 0.f; }

    const float* kb = Kbuf + ((size_t)b * SD) * ED + h * DH;
    const float* vb = Vbuf + ((size_t)b * SD) * ED + h * DH;

    for (int d0 = 0; d0 < DH; d0 += 32) {
#pragma unroll
        for (int u = 0; u < 4; u++) {
            int e = tid + 256 * u;
            int dd = e >> 5, i = e & 31;
            Ps[dd][i] = P[(size_t)(d0 + dd) * KPD + i];
        }
#pragma unroll
        for (int u = 0; u < 16; u++) {
            int e = tid + 256 * u;
            int s = e >> 5, dd = e & 31;
            Ks[s][dd] = kb[(size_t)s * ED + d0 + dd];
            Vs[s][dd] = vb[(size_t)s * ED + d0 + dd];
        }
        __syncthreads();

#pragma unroll
        for (int r = 0; r < 16; r++) {
            int e = tid + 256 * r;
            int i = e >> 7, s = e & 127;
            float ak = accK[r], av = accV[r];
#pragma unroll
            for (int dd = 0; dd < 32; dd++) {
                float p = Ps[dd][i];
                ak = fmaf(p, Ks[s][dd], ak);
                av = fmaf(p, Vs[s][dd], av);
            }
            accK[r] = ak; accV[r] = av;
        }
        __syncthreads();
    }

    const size_t base = (size_t)bh * (KPD * SD);
#pragma unroll
    for (int r = 0; r < 16; r++) {
        int e = tid + 256 * r;
        Kp[base + e] = accK[r];
        Vp[base + e] = accV[r];
    }
}

// ---------------------------------------------------------------------------
// Per-(b,h) attention (scores -> softmax(k=32) -> attn @ Vp)
// ---------------------------------------------------------------------------
__global__ void __launch_bounds__(128) attn_kernel(
    const float* __restrict__ Qbuf, const float* __restrict__ Kp,
    const float* __restrict__ Vp, float* __restrict__ AO)
{
    const int bh = blockIdx.x;
    const int b = bh >> 3, h = bh & 7;
    __shared__ float KpA[128 * 33];
    __shared__ float VpS[32 * 128];
    __shared__ float QS[128][17];

    const int tid = threadIdx.x;
    const size_t base = (size_t)bh * (KPD * SD);

#pragma unroll
    for (int u = 0; u < 32; u++) {
        int e = tid + 128 * u;
        KpA[e] = Kp[base + e];
        VpS[e] = Vp[base + e];
    }
    __syncthreads();

    float sc[32];
#pragma unroll
    for (int j = 0; j < 32; j++) sc[j] = 0.f;

    const float* qb = Qbuf + ((size_t)b * SD) * ED + h * DH;

    for (int d0 = 0; d0 < DH; d0 += 16) {
#pragma unroll
        for (int u = 0; u < 16; u++) {
            int e = tid + 128 * u;
            int s = e >> 4, dd = e & 15;
            QS[s][dd] = qb[(size_t)s * ED + d0 + dd];
        }
        __syncthreads();

        float q[16];
#pragma unroll
        for (int dd = 0; dd < 16; dd++) q[dd] = QS[tid][dd];
#pragma unroll
        for (int j = 0; j < 32; j++) {
            float p = 0.f;
#pragma unroll
            for (int dd = 0; dd < 16; dd++)
                p = fmaf(q[dd], KpA[j * 128 + d0 + dd], p);
            sc[j] += p;
        }
        __syncthreads();
    }

    const float scale = 0.08838834764831845f;  // 1/sqrt(128)
    float m = -1e30f;
#pragma unroll
    for (int j = 0; j < 32; j++) { sc[j] *= scale; m = fmaxf(m, sc[j]); }
    float sum = 0.f;
#pragma unroll
    for (int j = 0; j < 32; j++) { sc[j] = expf(sc[j] - m); sum += sc[j]; }
    float inv = 1.f / sum;

#pragma unroll
    for (int j = 0; j < 32; j++) KpA[tid * 33 + j] = sc[j] * inv;
    __syncthreads();

    float* ao = AO + ((size_t)b * SD) * ED + h * DH + tid;
    for (int r = 0; r < SD; r++) {
        float acc = 0.f;
#pragma unroll
        for (int j = 0; j < 32; j++)
            acc = fmaf(KpA[r * 33 + j], VpS[j * 128 + tid], acc);
        ao[(size_t)r * ED] = acc;
    }
}

// ---------------------------------------------------------------------------
extern "C" void kernel_launch(void* const* d_in, const int* in_sizes, int n_in,
                              void* d_out, int out_size)
{
    const float* x  = (const float*)d_in[0];
    const float* Wq = (const float*)d_in[1];
    const float* bq = (const float*)d_in[2];
    const float* Wk = (const float*)d_in[3];
    const float* bk = (const float*)d_in[4];
    const float* Wv = (const float*)d_in[5];
    const float* bv = (const float*)d_in[6];
    const float* P  = (const float*)d_in[7];
    const float* Wo = (const float*)d_in[8];
    const float* bo = (const float*)d_in[9];
    float* out = (float*)d_out;

    float *Qp, *Kbp, *Vbp, *AOp, *Kpp, *Vpp;
    cudaGetSymbolAddress((void**)&Qp,  g_Q);
    cudaGetSymbolAddress((void**)&Kbp, g_K);
    cudaGetSymbolAddress((void**)&Vbp, g_V);
    cudaGetSymbolAddress((void**)&AOp, g_AO);
    cudaGetSymbolAddress((void**)&Kpp, g_Kp);
    cudaGetSymbolAddress((void**)&Vpp, g_Vp);

    // Fused QKV projection (grid.z picks weight set)
    dim3 qkv_grid(ED / 128, MTOT / 128, 3);   // (8, 64, 3)
    gemm_tc<<<qkv_grid, 256>>>(x,
                               Wq, bq, Qp,
                               Wk, bk, Kbp,
                               Wv, bv, Vbp);

    proj_kernel<<<BD * HD_, 256>>>(Kbp, Vbp, P, Kpp, Vpp);
    attn_kernel<<<BD * HD_, 128>>>(Qp, Kpp, Vpp, AOp);

    // Output projection
    dim3 o_grid(ED / 128, MTOT / 128, 1);
    gemm_tc<<<o_grid, 256>>>(AOp,
                             Wo, bo, out,
                             Wo, bo, out,
                             Wo, bo, out);
}